// round 3
// baseline (speedup 1.0000x reference)
#include <cuda_runtime.h>
#include <math.h>

#define Bn 16
#define Nn 4096
#define Cn 512
#define Sn 8
#define Hn 8
#define HDn 64

// Scratch (static __device__ — no allocations).
// g_SA / g_SAS layout: [b][s*N + n']  (this IS the reinterpreted "sa" view)
__device__ __align__(16) float g_SA [Bn*Sn*Nn];
__device__ __align__(16) float g_SAS[Bn*Sn*Nn];
__device__ __align__(16) float g_tok[Bn*Sn*Cn];
__device__ __align__(16) float g_qkv[Bn*Sn*3*Cn];
__device__ __align__(16) float g_asp2[Bn*Sn*Cn];

__device__ __forceinline__ float wredmax(float v){
#pragma unroll
    for (int o = 16; o > 0; o >>= 1) v = fmaxf(v, __shfl_xor_sync(0xffffffffu, v, o));
    return v;
}
__device__ __forceinline__ float wredsum(float v){
#pragma unroll
    for (int o = 16; o > 0; o >>= 1) v += __shfl_xor_sync(0xffffffffu, v, o);
    return v;
}

// ---------------------------------------------------------------------------
// K1: fused space_attn GEMM + softmax.
// Block (b,s) computes space_attn rows n in [s*512,(s+1)*512) — exactly sa row s
// (flat reinterpretation) — then does the 4096-wide softmax in smem.
// ---------------------------------------------------------------------------
__global__ __launch_bounds__(256) void k1_sa_softmax(
    const float* __restrict__ x, const float* __restrict__ w_sum,
    const float* __restrict__ b_sum)
{
    __shared__ __align__(16) float ws[Sn*Cn];   // 16KB
    __shared__ float buf[4096];                  // 16KB
    __shared__ float red[16];
    const int t = threadIdx.x, lane = t & 31, w = t >> 5;
    const int b = blockIdx.x >> 3, s = blockIdx.x & 7;

    for (int i = t; i < Sn*Cn; i += 256) ws[i] = w_sum[i];
    float bsl = (lane < 8) ? b_sum[lane] : 0.f;
    __syncthreads();

    const float* xb = x + ((size_t)b*Nn + (size_t)s*512)*Cn;

    for (int g = 0; g < 16; g++) {
        const int base = g*32 + w*4;             // 4 rows per warp per group
        float4 xv[4][4];
#pragma unroll
        for (int r = 0; r < 4; r++) {
            const float4* xr = (const float4*)(xb + (size_t)(base + r)*Cn);
#pragma unroll
            for (int j = 0; j < 4; j++) xv[r][j] = xr[lane + 32*j];
        }
        float acc[4][8];
#pragma unroll
        for (int r = 0; r < 4; r++)
#pragma unroll
            for (int s2 = 0; s2 < 8; s2++) acc[r][s2] = 0.f;

#pragma unroll
        for (int j = 0; j < 4; j++) {
#pragma unroll
            for (int s2 = 0; s2 < 8; s2++) {
                float4 wv = ((const float4*)(ws + s2*Cn))[lane + 32*j];
#pragma unroll
                for (int r = 0; r < 4; r++) {
                    acc[r][s2] = fmaf(xv[r][j].x, wv.x, acc[r][s2]);
                    acc[r][s2] = fmaf(xv[r][j].y, wv.y, acc[r][s2]);
                    acc[r][s2] = fmaf(xv[r][j].z, wv.z, acc[r][s2]);
                    acc[r][s2] = fmaf(xv[r][j].w, wv.w, acc[r][s2]);
                }
            }
        }
#pragma unroll
        for (int r = 0; r < 4; r++)
#pragma unroll
            for (int s2 = 0; s2 < 8; s2++) {
                float v = wredsum(acc[r][s2]);
                if (lane == s2) buf[(base + r)*8 + s2] = v + bsl;
            }
    }
    __syncthreads();

    // softmax over the 4096 values
    float m = -3.4e38f;
    for (int i = t; i < 4096; i += 256) m = fmaxf(m, buf[i]);
    m = wredmax(m);
    if (!lane) red[w] = m;
    __syncthreads();
    float mf = red[0];
#pragma unroll
    for (int i = 1; i < 8; i++) mf = fmaxf(mf, red[i]);

    float zs = 0.f;
    for (int i = t; i < 4096; i += 256) zs += expf(buf[i] - mf);
    zs = wredsum(zs);
    if (!lane) red[8 + w] = zs;
    __syncthreads();
    float Z = 0.f;
#pragma unroll
    for (int i = 0; i < 8; i++) Z += red[8 + i];
    float invZ = 1.f / Z;

    float* sa  = g_SA  + ((size_t)b*Sn + s)*Nn;
    float* sas = g_SAS + ((size_t)b*Sn + s)*Nn;
    for (int i = t; i < 4096; i += 256) {
        float v = buf[i];
        sa[i]  = v;
        sas[i] = expf(v - mf) * invZ;
    }
}

// ---------------------------------------------------------------------------
// K3: tokens[b,s,c] = max_n prob[b,s,n] * x_flat[b][c*N + n]
// Block (b, 8 c's); 64 running maxes per thread in registers.
// ---------------------------------------------------------------------------
__global__ __launch_bounds__(256) void k3_tokens(const float* __restrict__ x)
{
    const int t = threadIdx.x, lane = t & 31, w = t >> 5;
    const int b = blockIdx.y, c0 = blockIdx.x * 8;
    const float* xb = x + (size_t)b*Nn*Cn;       // X2 view: xb[c*N + n]
    const float* pb = g_SAS + (size_t)b*Sn*Nn;

    float mx[64];
#pragma unroll
    for (int k = 0; k < 64; k++) mx[k] = -3.4e38f;

    for (int i = 0; i < 16; i++) {
        int n = t + (i << 8);
        float p[8], xv[8];
#pragma unroll
        for (int s2 = 0; s2 < 8; s2++) p[s2] = pb[(size_t)s2*Nn + n];
#pragma unroll
        for (int c = 0; c < 8; c++) xv[c] = xb[(size_t)(c0 + c)*Nn + n];
#pragma unroll
        for (int c = 0; c < 8; c++)
#pragma unroll
            for (int s2 = 0; s2 < 8; s2++)
                mx[c*8 + s2] = fmaxf(mx[c*8 + s2], p[s2] * xv[c]);
    }
#pragma unroll
    for (int k = 0; k < 64; k++) mx[k] = wredmax(mx[k]);

    __shared__ float red[8][64];
    if (!lane) {
#pragma unroll
        for (int k = 0; k < 64; k++) red[w][k] = mx[k];
    }
    __syncthreads();
    if (t < 64) {
        float v = red[0][t];
#pragma unroll
        for (int w2 = 1; w2 < 8; w2++) v = fmaxf(v, red[w2][t]);
        int c = t >> 3, s2 = t & 7;
        g_tok[((size_t)b*Sn + s2)*Cn + c0 + c] = v;
    }
}

// ---------------------------------------------------------------------------
// K4a: qkv[b,r,j] = sum_k tokens[b,r,k] * w_qkv[j,k]   (j over 3C=1536)
// Warp-cooperative, 4 output cols x 8 rows at a time.
// ---------------------------------------------------------------------------
__global__ __launch_bounds__(256) void k4a_qkv(const float* __restrict__ w_qkv)
{
    __shared__ __align__(16) float tokS[Sn*Cn];  // [r][k], 16KB
    const int t = threadIdx.x, lane = t & 31, w = t >> 5;
    const int b = blockIdx.y, j0 = blockIdx.x * 128;

    for (int i = t; i < Sn*Cn; i += 256) tokS[i] = g_tok[(size_t)b*Sn*Cn + i];
    __syncthreads();

    for (int cc = 0; cc < 4; cc++) {
        int j = j0 + w*16 + cc*4;
        float acc[4][8];
#pragma unroll
        for (int q = 0; q < 4; q++)
#pragma unroll
            for (int r = 0; r < 8; r++) acc[q][r] = 0.f;

#pragma unroll
        for (int ch = 0; ch < 4; ch++) {
            float4 tv[8];
#pragma unroll
            for (int r = 0; r < 8; r++)
                tv[r] = ((const float4*)(tokS + r*Cn))[lane + 32*ch];
#pragma unroll
            for (int q = 0; q < 4; q++) {
                float4 wv = ((const float4*)(w_qkv + (size_t)(j + q)*Cn))[lane + 32*ch];
#pragma unroll
                for (int r = 0; r < 8; r++) {
                    acc[q][r] = fmaf(wv.x, tv[r].x, acc[q][r]);
                    acc[q][r] = fmaf(wv.y, tv[r].y, acc[q][r]);
                    acc[q][r] = fmaf(wv.z, tv[r].z, acc[q][r]);
                    acc[q][r] = fmaf(wv.w, tv[r].w, acc[q][r]);
                }
            }
        }
#pragma unroll
        for (int q = 0; q < 4; q++)
#pragma unroll
            for (int r = 0; r < 8; r++) {
                float v = wredsum(acc[q][r]);
                if (lane == r)
                    g_qkv[((size_t)b*Sn + r)*(3*Cn) + j + q] = v;
            }
    }
}

// ---------------------------------------------------------------------------
// K4b: per-batch 8x8 attention (H=8 heads, hd=64) + cross mixing.
// ---------------------------------------------------------------------------
__global__ __launch_bounds__(256) void k4b_attn(const float* __restrict__ w_cross)
{
    __shared__ float sc[512];                    // [h][i][j]
    __shared__ float aspS[Sn*Cn];                // [s][c], 16KB
    __shared__ float wc[64];
    const int t = threadIdx.x, b = blockIdx.x;
    const float* qkvb = g_qkv + (size_t)b*Sn*3*Cn;

    if (t < 64) wc[t] = w_cross[t];

#pragma unroll
    for (int u = 0; u < 2; u++) {
        int idx = t + u*256;                     // h*64 + i*8 + j
        int h = idx >> 6, i2 = (idx >> 3) & 7, j = idx & 7;
        const float4* qp = (const float4*)(qkvb + i2*1536 + h*64);
        const float4* kp = (const float4*)(qkvb + j*1536 + 512 + h*64);
        float a = 0.f;
#pragma unroll
        for (int d = 0; d < 16; d++) {
            float4 qq = qp[d], kk = kp[d];
            a = fmaf(qq.x, kk.x, a); a = fmaf(qq.y, kk.y, a);
            a = fmaf(qq.z, kk.z, a); a = fmaf(qq.w, kk.w, a);
        }
        sc[idx] = a * 0.125f;                    // scale = hd^-0.5
    }
    __syncthreads();
    if (t < 64) {                                // softmax over j (8)
        float* row = sc + t*8;
        float m = row[0];
#pragma unroll
        for (int j = 1; j < 8; j++) m = fmaxf(m, row[j]);
        float e[8], zz = 0.f;
#pragma unroll
        for (int j = 0; j < 8; j++) { e[j] = expf(row[j] - m); zz += e[j]; }
        float iz = 1.f / zz;
#pragma unroll
        for (int j = 0; j < 8; j++) row[j] = e[j] * iz;
    }
    __syncthreads();
    for (int u = 0; u < 16; u++) {               // asp = attn @ v, layout [s][c]
        int idx = t + u*256;
        int si = idx >> 9, c = idx & 511, h = c >> 6;
        float a = 0.f;
#pragma unroll
        for (int j = 0; j < 8; j++)
            a = fmaf(sc[h*64 + si*8 + j], qkvb[j*1536 + 1024 + c], a);
        aspS[idx] = a;
    }
    __syncthreads();
    float* a2o = g_asp2 + (size_t)b*Sn*Cn;
    for (int u = 0; u < 16; u++) {               // cross: asp2[s,c]=sum_s' wc[s,s']*asp[s',c]
        int idx = t + u*256;
        int si = idx >> 9, c = idx & 511;
        float o = 0.f;
#pragma unroll
        for (int sp = 0; sp < 8; sp++)
            o = fmaf(wc[si*8 + sp], aspS[sp*512 + c], o);
        a2o[idx] = o;
    }
}

// ---------------------------------------------------------------------------
// K5: out[b,n,:] = LN( sum_s sa[b,n,s]*asp2[b,s,:] )*gamma + beta + x[b,n,:]
// Warp per row: no block-level syncs in the row loop.
// ---------------------------------------------------------------------------
__global__ __launch_bounds__(256) void k5_final(
    const float* __restrict__ x, const float* __restrict__ gamma,
    const float* __restrict__ beta, float* __restrict__ out)
{
    __shared__ __align__(16) float a2[Sn*Cn];    // 16KB
    __shared__ __align__(16) float gS[Cn], bS[Cn];
    const int t = threadIdx.x, lane = t & 31, w = t >> 5;
    const int b = blockIdx.y, n0 = blockIdx.x * 32;

    for (int i = t; i < Sn*Cn; i += 256) a2[i] = g_asp2[(size_t)b*Sn*Cn + i];
    for (int i = t; i < Cn; i += 256) { gS[i] = gamma[i]; bS[i] = beta[i]; }
    __syncthreads();

    const float* sab = g_SA + (size_t)b*Sn*Nn;
    for (int rr = 0; rr < 4; rr++) {
        int n = n0 + w*4 + rr;
        float p[8];
#pragma unroll
        for (int s2 = 0; s2 < 8; s2++) p[s2] = sab[(size_t)s2*Nn + n];

        const float4* xr = (const float4*)(x + ((size_t)b*Nn + n)*Cn);
        float4 xv[4], tv[4];
#pragma unroll
        for (int j = 0; j < 4; j++) xv[j] = xr[lane + 32*j];

        float sum = 0.f;
#pragma unroll
        for (int j = 0; j < 4; j++) {
            float4 v = make_float4(0.f, 0.f, 0.f, 0.f);
#pragma unroll
            for (int s2 = 0; s2 < 8; s2++) {
                float4 a = ((const float4*)(a2 + s2*Cn))[lane + 32*j];
                v.x = fmaf(p[s2], a.x, v.x);
                v.y = fmaf(p[s2], a.y, v.y);
                v.z = fmaf(p[s2], a.z, v.z);
                v.w = fmaf(p[s2], a.w, v.w);
            }
            tv[j] = v;
            sum += v.x + v.y + v.z + v.w;
        }
        sum = wredsum(sum);
        float mu = sum * (1.0f/512.0f);
        float sq = 0.f;
#pragma unroll
        for (int j = 0; j < 4; j++) {
            float dx_ = tv[j].x - mu, dy = tv[j].y - mu, dz = tv[j].z - mu, dw = tv[j].w - mu;
            sq = fmaf(dx_, dx_, sq); sq = fmaf(dy, dy, sq);
            sq = fmaf(dz, dz, sq);   sq = fmaf(dw, dw, sq);
        }
        sq = wredsum(sq);
        float var = sq * (1.0f/512.0f);
        float rs = rsqrtf(var + 1e-5f);

        float4* orow = (float4*)(out + ((size_t)b*Nn + n)*Cn);
#pragma unroll
        for (int j = 0; j < 4; j++) {
            float4 g4 = ((const float4*)gS)[lane + 32*j];
            float4 b4 = ((const float4*)bS)[lane + 32*j];
            float4 o;
            o.x = (tv[j].x - mu)*rs*g4.x + b4.x + xv[j].x;
            o.y = (tv[j].y - mu)*rs*g4.y + b4.y + xv[j].y;
            o.z = (tv[j].z - mu)*rs*g4.z + b4.z + xv[j].z;
            o.w = (tv[j].w - mu)*rs*g4.w + b4.w + xv[j].w;
            orow[lane + 32*j] = o;
        }
    }
}

// ---------------------------------------------------------------------------
extern "C" void kernel_launch(void* const* d_in, const int* in_sizes, int n_in,
                              void* d_out, int out_size)
{
    const float* x       = (const float*)d_in[0];
    const float* w_sum   = (const float*)d_in[1];
    const float* b_sum   = (const float*)d_in[2];
    const float* w_qkv   = (const float*)d_in[3];
    const float* w_cross = (const float*)d_in[4];
    const float* gamma   = (const float*)d_in[5];
    const float* beta    = (const float*)d_in[6];
    float* out = (float*)d_out;

    k1_sa_softmax<<<Bn*Sn, 256>>>(x, w_sum, b_sum);
    k3_tokens<<<dim3(Cn/8, Bn), 256>>>(x);
    k4a_qkv<<<dim3(12, Bn), 256>>>(w_qkv);
    k4b_attn<<<Bn, 256>>>(w_cross);
    k5_final<<<dim3(Nn/32, Bn), 256>>>(x, gamma, beta, out);
}